// round 7
// baseline (speedup 1.0000x reference)
#include <cuda_runtime.h>
#include <cuda_bf16.h>
#include <cstdint>
#include <math.h>

#define BB   2
#define SS   1024
#define DMODEL 1024
#define NH   16
#define NLAYER 4
#define DFFN 4096
#define HDIM 64
#define NTOK (BB*SS)          // 2048
#define NREL (2*SS-1)         // 2047

// ---------------- static scratch ----------------
__device__ float          g_X  [NTOK*DMODEL];            // fp32 activations
__device__ __nv_bfloat16  g_Xs [NTOK*2*DMODEL];          // split of layer input
__device__ __nv_bfloat16  g_Qs [NTOK*2*DMODEL];
__device__ __nv_bfloat16  g_Ks [NTOK*2*DMODEL];          // split of K' = K/8 + Ebar
__device__ float          g_V  [NTOK*DMODEL];
__device__ __nv_bfloat16  g_VTs[(size_t)BB*NH*HDIM*2*SS];// per-head V^T split
__device__ float          g_P  [(size_t)BB*NH*SS*SS];    // scores fp32
__device__ __nv_bfloat16  g_Ps [(size_t)BB*NH*SS*2*SS];  // probs split
__device__ __nv_bfloat16  g_AOs[NTOK*2*DMODEL];
__device__ float          g_T1 [NTOK*DMODEL];
__device__ float          g_X1 [NTOK*DMODEL];
__device__ __nv_bfloat16  g_X1s[NTOK*2*DMODEL];
__device__ __nv_bfloat16  g_Hs [(size_t)NTOK*2*DFFN];
__device__ __nv_bfloat16  g_Ws [(size_t)DFFN*2*DMODEL];  // weight split scratch (16MB)
__device__ float          g_EB [SS*HDIM];

// ---------------- helpers ----------------
__device__ __forceinline__ uint32_t smem_to_u32(const void* p) {
    uint32_t a;
    asm("{ .reg .u64 t; cvta.to.shared.u64 t, %1; cvt.u32.u64 %0, t; }" : "=r"(a) : "l"(p));
    return a;
}
__device__ __forceinline__ void cp_async16(uint32_t s, const void* g) {
    asm volatile("cp.async.cg.shared.global [%0], [%1], 16;" :: "r"(s), "l"(g) : "memory");
}
#define CP_COMMIT() asm volatile("cp.async.commit_group;" ::: "memory")
#define CP_WAIT(n)  asm volatile("cp.async.wait_group %0;" :: "n"(n) : "memory")

__device__ __forceinline__ void ldsm_x4(uint32_t addr, uint32_t& r0, uint32_t& r1,
                                        uint32_t& r2, uint32_t& r3) {
    asm volatile("ldmatrix.sync.aligned.m8n8.x4.shared.b16 {%0,%1,%2,%3}, [%4];"
                 : "=r"(r0), "=r"(r1), "=r"(r2), "=r"(r3) : "r"(addr));
}
__device__ __forceinline__ void mma16816(float* c, const uint32_t* a, uint32_t b0, uint32_t b1) {
    asm volatile(
        "mma.sync.aligned.m16n8k16.row.col.f32.bf16.bf16.f32 "
        "{%0,%1,%2,%3}, {%4,%5,%6,%7}, {%8,%9}, {%0,%1,%2,%3};"
        : "+f"(c[0]), "+f"(c[1]), "+f"(c[2]), "+f"(c[3])
        : "r"(a[0]), "r"(a[1]), "r"(a[2]), "r"(a[3]), "r"(b0), "r"(b1));
}

struct __align__(8) bh4 { __nv_bfloat16 h[4]; };
__device__ __forceinline__ void split2(float v, __nv_bfloat16& hi, __nv_bfloat16& lo) {
    hi = __float2bfloat16(v);
    lo = __float2bfloat16(v - __bfloat162float(hi));
}

// =======================================================================
// HMMA split-fp32 GEMM: C = A * B^T with 3-term error compensation.
// A, B stored as [hi(K) | lo(K)] bf16 rows.  Stage t: i=t/3, j=t%3:
//   (hiA,hiB), (hiA,loB), (loA,hiB)  => error ~2^-16.
// block tile 128 x NT, 8 warps = 4(m) x 2(n).
// STAGES=2: proven double-buffer (2 syncs/stage).
// STAGES=3: ring pipeline, ONE sync/stage, load t+2 issued at stage t.
// EPI: 0 = f32+bias, 1 = split+bias, 2 = split+bias+gelu, 3 = split+bias+kadjust
// =======================================================================
template<int NT, int STAGES, int EPI>
__global__ void __launch_bounds__(256) mma_gemm(
    const __nv_bfloat16* __restrict__ A, long lda, long csA, long loA,
    const __nv_bfloat16* __restrict__ B, long ldb, long csB, long loB,
    const float* __restrict__ bias, const float* __restrict__ EB,
    void* __restrict__ Cv, long ldc, long loOff,
    int T, int zdivAB, long sA1, long sA2, long sB1, long sB2,
    int zdivC, long sC1, long sC2)
{
    extern __shared__ __align__(16) char smraw[];
    constexpr int LDS = 72;                   // bf16 elems per smem row (144B)
    constexpr int ASZ = 128 * LDS * 2;        // bytes per A tile
    constexpr int BSZ = NT  * LDS * 2;
    constexpr int STAGE = ASZ + BSZ;

    const int tid = threadIdx.x;
    const int z = blockIdx.z;
    A += (long)(z / zdivAB) * sA1 + (long)(z % zdivAB) * sA2;
    B += (long)(z / zdivAB) * sB1 + (long)(z % zdivAB) * sB2;
    const long co = (long)(z / zdivC) * sC1 + (long)(z % zdivC) * sC2;
    const int m0 = blockIdx.y * 128, n0 = blockIdx.x * NT;

    const int lane = tid & 31, wid = tid >> 5;
    const int warp_m = wid & 3, warp_n = wid >> 2;

    auto load_stage = [&](int buf, int t) {
        const int i3 = t / 3, j3 = t - 3 * i3;
        const long colA = (long)i3 * csA + (j3 == 2 ? loA : 0);
        const long colB = (long)i3 * csB + (j3 == 1 ? loB : 0);
        const uint32_t sa = smem_to_u32(smraw + (long)buf * STAGE);
        #pragma unroll
        for (int i = 0; i < 4; i++) {
            const int idx = tid + i * 256;
            const int row = idx >> 3, c = idx & 7;
            cp_async16(sa + row * (LDS * 2) + c * 16,
                       A + (long)(m0 + row) * lda + colA + c * 8);
        }
        const uint32_t sb = sa + ASZ;
        #pragma unroll
        for (int i = 0; i < NT / 32; i++) {
            const int idx = tid + i * 256;
            const int row = idx >> 3, c = idx & 7;
            cp_async16(sb + row * (LDS * 2) + c * 16,
                       B + (long)(n0 + row) * ldb + colB + c * 8);
        }
        CP_COMMIT();
    };

    float acc[2][NT / 16][4];
    #pragma unroll
    for (int mi = 0; mi < 2; mi++)
        #pragma unroll
        for (int ni = 0; ni < NT / 16; ni++)
            #pragma unroll
            for (int j = 0; j < 4; j++) acc[mi][ni][j] = 0.f;

    // ldmatrix lane selectors
    const int aRow = (lane & 7) + ((lane >> 3) & 1) * 8;   // within m16
    const int aK   = (lane >> 4) * 8;                      // within k16
    const int bN   = ((lane >> 4) * 8) + (lane & 7);       // within n16
    const int bK   = ((lane >> 3) & 1) * 8;                // within k16

    auto compute_stage = [&](int buf) {
        const uint32_t sa = smem_to_u32(smraw + (long)buf * STAGE);
        const uint32_t sb = sa + ASZ;
        #pragma unroll
        for (int k16 = 0; k16 < 4; k16++) {
            uint32_t afr[2][4];
            #pragma unroll
            for (int mi = 0; mi < 2; mi++) {
                const int m = warp_m * 32 + mi * 16 + aRow;
                const int k = k16 * 16 + aK;
                ldsm_x4(sa + (m * LDS + k) * 2, afr[mi][0], afr[mi][1], afr[mi][2], afr[mi][3]);
            }
            uint32_t bfr[NT / 32][4];
            #pragma unroll
            for (int nb = 0; nb < NT / 32; nb++) {
                const int n = warp_n * (NT / 2) + nb * 16 + bN;
                const int k = k16 * 16 + bK;
                ldsm_x4(sb + (n * LDS + k) * 2, bfr[nb][0], bfr[nb][1], bfr[nb][2], bfr[nb][3]);
            }
            #pragma unroll
            for (int mi = 0; mi < 2; mi++)
                #pragma unroll
                for (int ni = 0; ni < NT / 16; ni++)
                    mma16816(acc[mi][ni], afr[mi],
                             bfr[ni >> 1][(ni & 1) * 2], bfr[ni >> 1][(ni & 1) * 2 + 1]);
        }
    };

    if (STAGES == 2) {
        load_stage(0, 0);
        for (int t = 0; t < T; t++) {
            if (t + 1 < T) { load_stage((t + 1) & 1, t + 1); CP_WAIT(1); }
            else           { CP_WAIT(0); }
            __syncthreads();
            compute_stage(t & 1);
            __syncthreads();
        }
    } else {
        // 3-stage ring, one barrier per stage
        load_stage(0, 0);
        if (T > 1) load_stage(1, 1);
        for (int t = 0; t < T; t++) {
            if (t + 1 < T) { CP_WAIT(1); } else { CP_WAIT(0); }
            __syncthreads();
            if (t + 2 < T) load_stage((t + 2) % 3, t + 2);
            compute_stage(t % 3);
        }
    }

    // ---------------- epilogue ----------------
    const int g = lane >> 2, tig = lane & 3;
    #pragma unroll
    for (int mi = 0; mi < 2; mi++) {
        #pragma unroll
        for (int ni = 0; ni < NT / 16; ni++) {
            #pragma unroll
            for (int half = 0; half < 2; half++) {
                const int r = m0 + warp_m * 32 + mi * 16 + g + half * 8;
                const int c = n0 + warp_n * (NT / 2) + ni * 8 + tig * 2;
                float v0 = acc[mi][ni][half * 2 + 0];
                float v1 = acc[mi][ni][half * 2 + 1];
                if (bias) { v0 += bias[c]; v1 += bias[c + 1]; }
                if (EPI == 3) {
                    const int sr = (r & (SS - 1)) * HDIM;
                    v0 = v0 * 0.125f + EB[sr + (c & (HDIM - 1))];
                    v1 = v1 * 0.125f + EB[sr + ((c + 1) & (HDIM - 1))];
                }
                if (EPI == 2) {
                    v0 = 0.5f * v0 * (1.0f + erff(v0 * 0.70710678118654752f));
                    v1 = 0.5f * v1 * (1.0f + erff(v1 * 0.70710678118654752f));
                }
                if (EPI == 0) {
                    float* C = (float*)Cv + co;
                    float2 o; o.x = v0; o.y = v1;
                    *(float2*)&C[(long)r * ldc + c] = o;
                } else {
                    __nv_bfloat16* Cs = (__nv_bfloat16*)Cv + co;
                    __nv_bfloat16 h0, l0, h1, l1;
                    split2(v0, h0, l0); split2(v1, h1, l1);
                    __nv_bfloat162 hp, lp;
                    hp.x = h0; hp.y = h1; lp.x = l0; lp.y = l1;
                    *(__nv_bfloat162*)&Cs[(long)r * ldc + c]         = hp;
                    *(__nv_bfloat162*)&Cs[(long)r * ldc + c + loOff] = lp;
                }
            }
        }
    }
}

// ---------------- reductions ----------------
__device__ __forceinline__ float block_reduce_sum(float v, float* sh) {
    #pragma unroll
    for (int o = 16; o; o >>= 1) v += __shfl_xor_sync(0xffffffffu, v, o);
    int warp = threadIdx.x >> 5, lane = threadIdx.x & 31;
    if (lane == 0) sh[warp] = v;
    __syncthreads();
    if (threadIdx.x < 8) {
        float x = sh[threadIdx.x];
        #pragma unroll
        for (int o = 4; o; o >>= 1) x += __shfl_xor_sync(0xffu, x, o);
        if (threadIdx.x == 0) sh[0] = x;
    }
    __syncthreads();
    float r = sh[0];
    __syncthreads();
    return r;
}
__device__ __forceinline__ float block_reduce_max(float v, float* sh) {
    #pragma unroll
    for (int o = 16; o; o >>= 1) v = fmaxf(v, __shfl_xor_sync(0xffffffffu, v, o));
    int warp = threadIdx.x >> 5, lane = threadIdx.x & 31;
    if (lane == 0) sh[warp] = v;
    __syncthreads();
    if (threadIdx.x < 8) {
        float x = sh[threadIdx.x];
        #pragma unroll
        for (int o = 4; o; o >>= 1) x = fmaxf(x, __shfl_xor_sync(0xffu, x, o));
        if (threadIdx.x == 0) sh[0] = x;
    }
    __syncthreads();
    float r = sh[0];
    __syncthreads();
    return r;
}

// ---------------- Ebar ----------------
__global__ void ebar_kernel(const float* __restrict__ rel) {
    const int j = blockIdx.x, d = threadIdx.x;
    const float* r0 = rel + (long)(SS - 1 - j) * HDIM + d;
    float s = 0.f;
    #pragma unroll 4
    for (int k = 0; k < SS; k++) s += r0[(long)k * HDIM];
    g_EB[j * HDIM + d] = s * (1.0f / SS);
}

// ---------------- split fp32 [R,K] -> bf16 [R, 2K] ----------------
__global__ void __launch_bounds__(256) split_kernel(
    const float* __restrict__ in, __nv_bfloat16* __restrict__ out, long n, int kshift)
{
    const long i4 = ((long)blockIdx.x * 256 + threadIdx.x) * 4;
    if (i4 >= n) return;
    const long row = i4 >> kshift;
    const int  K   = 1 << kshift;
    const int  col = (int)(i4 & (K - 1));
    const float4 v = *(const float4*)&in[i4];
    bh4 hi, lo;
    split2(v.x, hi.h[0], lo.h[0]); split2(v.y, hi.h[1], lo.h[1]);
    split2(v.z, hi.h[2], lo.h[2]); split2(v.w, hi.h[3], lo.h[3]);
    *(bh4*)&out[row * 2 * K + col]     = hi;
    *(bh4*)&out[row * 2 * K + K + col] = lo;
}

// ---------------- V -> per-head V^T split ----------------
__global__ void split_transpose_v(const float* __restrict__ V, __nv_bfloat16* __restrict__ VT) {
    __shared__ float t[32][33];
    const int bh = blockIdx.z, b = bh >> 4, h = bh & 15;
    const int s0 = blockIdx.x * 32, d0 = blockIdx.y * 32;
    const int tx = threadIdx.x, ty = threadIdx.y;
    #pragma unroll
    for (int r = 0; r < 4; r++) {
        const int s = s0 + ty + r * 8;
        t[ty + r * 8][tx] = V[((long)b * SS + s) * DMODEL + h * HDIM + d0 + tx];
    }
    __syncthreads();
    #pragma unroll
    for (int r = 0; r < 4; r++) {
        const int d = d0 + ty + r * 8;
        const int s = s0 + tx;
        const float v = t[tx][ty + r * 8];
        __nv_bfloat16 hi, lo; split2(v, hi, lo);
        VT[((long)bh * HDIM + d) * (2 * SS) + s]      = hi;
        VT[((long)bh * HDIM + d) * (2 * SS) + SS + s] = lo;
    }
}

// ---------------- softmax (fp32 in) -> split bf16 out ----------------
__global__ void __launch_bounds__(256) softmax_split_kernel(
    const float* __restrict__ P, __nv_bfloat16* __restrict__ Ps)
{
    __shared__ float sh[8];
    const float* p = P + (long)blockIdx.x * SS;
    __nv_bfloat16* q = Ps + (long)blockIdx.x * (2 * SS);
    const int t = threadIdx.x;
    float4 v = *(const float4*)&p[t * 4];
    float m = fmaxf(fmaxf(v.x, v.y), fmaxf(v.z, v.w));
    m = block_reduce_max(m, sh);
    v.x = expf(v.x - m); v.y = expf(v.y - m);
    v.z = expf(v.z - m); v.w = expf(v.w - m);
    float s = v.x + v.y + v.z + v.w;
    s = block_reduce_sum(s, sh);
    const float inv = 1.0f / s;
    v.x *= inv; v.y *= inv; v.z *= inv; v.w *= inv;
    bh4 hi, lo;
    split2(v.x, hi.h[0], lo.h[0]); split2(v.y, hi.h[1], lo.h[1]);
    split2(v.z, hi.h[2], lo.h[2]); split2(v.w, hi.h[3], lo.h[3]);
    *(bh4*)&q[t * 4]      = hi;
    *(bh4*)&q[SS + t * 4] = lo;
}

// ---------------- LN(xin + add) -> fp32 out + split out ----------------
__global__ void __launch_bounds__(256) ln_kernel(
    const float* __restrict__ xin, const float* __restrict__ add,
    const float* __restrict__ g, const float* __restrict__ be,
    float* __restrict__ out, __nv_bfloat16* __restrict__ outs)
{
    __shared__ float sh[8];
    const long row = blockIdx.x;
    const int t = threadIdx.x;
    const float4 a  = *(const float4*)&xin[row * DMODEL + t * 4];
    const float4 b2 = *(const float4*)&add[row * DMODEL + t * 4];
    float y[4] = {a.x + b2.x, a.y + b2.y, a.z + b2.z, a.w + b2.w};
    float s = y[0] + y[1] + y[2] + y[3];
    s = block_reduce_sum(s, sh);
    const float mean = s * (1.0f / DMODEL);
    float q = 0.f;
    #pragma unroll
    for (int i = 0; i < 4; i++) { const float d = y[i] - mean; q += d * d; }
    q = block_reduce_sum(q, sh);
    const float rstd = rsqrtf(q * (1.0f / DMODEL) + 1e-5f);
    const float4 gg = *(const float4*)&g[t * 4];
    const float4 bb = *(const float4*)&be[t * 4];
    float o[4];
    o[0] = (y[0] - mean) * rstd * gg.x + bb.x;
    o[1] = (y[1] - mean) * rstd * gg.y + bb.y;
    o[2] = (y[2] - mean) * rstd * gg.z + bb.z;
    o[3] = (y[3] - mean) * rstd * gg.w + bb.w;
    *(float4*)&out[row * DMODEL + t * 4] = *(float4*)o;
    bh4 hi, lo;
    #pragma unroll
    for (int i = 0; i < 4; i++) split2(o[i], hi.h[i], lo.h[i]);
    *(bh4*)&outs[row * 2 * DMODEL + t * 4]          = hi;
    *(bh4*)&outs[row * 2 * DMODEL + DMODEL + t * 4] = lo;
}

// ---------------- host ----------------
extern "C" void kernel_launch(void* const* d_in, const int* in_sizes, int n_in,
                              void* d_out, int out_size)
{
    (void)in_sizes; (void)n_in; (void)out_size;
    const float* x   = (const float*)d_in[0];
    const float* Wq  = (const float*)d_in[1];
    const float* bq  = (const float*)d_in[2];
    const float* Wk  = (const float*)d_in[3];
    const float* bk  = (const float*)d_in[4];
    const float* Wv  = (const float*)d_in[5];
    const float* bv  = (const float*)d_in[6];
    const float* Wo  = (const float*)d_in[7];
    const float* bo  = (const float*)d_in[8];
    const float* rel = (const float*)d_in[9];
    const float* W1  = (const float*)d_in[10];
    const float* b1  = (const float*)d_in[11];
    const float* W2  = (const float*)d_in[12];
    const float* b2  = (const float*)d_in[13];
    const float* g1  = (const float*)d_in[14];
    const float* be1 = (const float*)d_in[15];
    const float* g2  = (const float*)d_in[16];
    const float* be2 = (const float*)d_in[17];
    float* out = (float*)d_out;

    float *pX, *pV, *pP, *pT1, *pX1, *pEB;
    __nv_bfloat16 *pXs, *pQs, *pKs, *pVTs, *pPs, *pAOs, *pX1s, *pHs, *pWs;
    cudaGetSymbolAddress((void**)&pX,   g_X);
    cudaGetSymbolAddress((void**)&pXs,  g_Xs);
    cudaGetSymbolAddress((void**)&pQs,  g_Qs);
    cudaGetSymbolAddress((void**)&pKs,  g_Ks);
    cudaGetSymbolAddress((void**)&pV,   g_V);
    cudaGetSymbolAddress((void**)&pVTs, g_VTs);
    cudaGetSymbolAddress((void**)&pP,   g_P);
    cudaGetSymbolAddress((void**)&pPs,  g_Ps);
    cudaGetSymbolAddress((void**)&pAOs, g_AOs);
    cudaGetSymbolAddress((void**)&pT1,  g_T1);
    cudaGetSymbolAddress((void**)&pX1,  g_X1);
    cudaGetSymbolAddress((void**)&pX1s, g_X1s);
    cudaGetSymbolAddress((void**)&pHs,  g_Hs);
    cudaGetSymbolAddress((void**)&pWs,  g_Ws);
    cudaGetSymbolAddress((void**)&pEB,  g_EB);

    constexpr int LDS = 72;
    const int SMEM128 = 2 * (128 + 128) * LDS * 2;   // 73728  (2-stage)
    const int SMEM64  = 3 * (128 + 64)  * LDS * 2;   // 82944  (3-stage)
    cudaFuncSetAttribute((void*)mma_gemm<128,2,0>, cudaFuncAttributeMaxDynamicSharedMemorySize, SMEM128);
    cudaFuncSetAttribute((void*)mma_gemm<128,2,2>, cudaFuncAttributeMaxDynamicSharedMemorySize, SMEM128);
    cudaFuncSetAttribute((void*)mma_gemm<64,3,0>,  cudaFuncAttributeMaxDynamicSharedMemorySize, SMEM64);
    cudaFuncSetAttribute((void*)mma_gemm<64,3,1>,  cudaFuncAttributeMaxDynamicSharedMemorySize, SMEM64);
    cudaFuncSetAttribute((void*)mma_gemm<64,3,3>,  cudaFuncAttributeMaxDynamicSharedMemorySize, SMEM64);

    const dim3 blk(256);

    // split the initial input once
    split_kernel<<<(NTOK * DMODEL) / 1024, blk>>>(x, pXs, (long)NTOK * DMODEL, 10);

    for (int l = 0; l < NLAYER; l++) {
        const float* xin  = (l == 0) ? x : pX;
        const float* Wq_l = Wq + (long)l * DMODEL * DMODEL;
        const float* Wk_l = Wk + (long)l * DMODEL * DMODEL;
        const float* Wv_l = Wv + (long)l * DMODEL * DMODEL;
        const float* Wo_l = Wo + (long)l * DMODEL * DMODEL;
        const float* W1_l = W1 + (long)l * DFFN * DMODEL;
        const float* W2_l = W2 + (long)l * DMODEL * DFFN;
        const float* bq_l = bq + (long)l * DMODEL;
        const float* bk_l = bk + (long)l * DMODEL;
        const float* bv_l = bv + (long)l * DMODEL;
        const float* bo_l = bo + (long)l * DMODEL;
        const float* b1_l = b1 + (long)l * DFFN;
        const float* b2_l = b2 + (long)l * DMODEL;
        const float* g1_l = g1 + (long)l * DMODEL;
        const float* be1_l= be1+ (long)l * DMODEL;
        const float* g2_l = g2 + (long)l * DMODEL;
        const float* be2_l= be2+ (long)l * DMODEL;
        const float* rel_l= rel+ (long)l * NREL * HDIM;

        ebar_kernel<<<SS, HDIM>>>(rel_l);

        // Q projection -> split Qs   (NT=64, 3-stage: grid 16x16 = 256 CTAs)
        split_kernel<<<(DMODEL * DMODEL) / 1024, blk>>>(Wq_l, pWs, (long)DMODEL * DMODEL, 10);
        mma_gemm<64,3,1><<<dim3(16,16,1), blk, SMEM64>>>(
            pXs, 2*DMODEL, 64, DMODEL, pWs, 2*DMODEL, 64, DMODEL, bq_l, nullptr,
            pQs, 2*DMODEL, DMODEL, 48, 1, 0,0,0,0, 1, 0,0);

        // K projection -> K' = K/8 + Ebar -> split Ks
        split_kernel<<<(DMODEL * DMODEL) / 1024, blk>>>(Wk_l, pWs, (long)DMODEL * DMODEL, 10);
        mma_gemm<64,3,3><<<dim3(16,16,1), blk, SMEM64>>>(
            pXs, 2*DMODEL, 64, DMODEL, pWs, 2*DMODEL, 64, DMODEL, bk_l, pEB,
            pKs, 2*DMODEL, DMODEL, 48, 1, 0,0,0,0, 1, 0,0);

        // V projection -> fp32 V
        split_kernel<<<(DMODEL * DMODEL) / 1024, blk>>>(Wv_l, pWs, (long)DMODEL * DMODEL, 10);
        mma_gemm<64,3,0><<<dim3(16,16,1), blk, SMEM64>>>(
            pXs, 2*DMODEL, 64, DMODEL, pWs, 2*DMODEL, 64, DMODEL, bv_l, nullptr,
            pV, DMODEL, 0, 48, 1, 0,0,0,0, 1, 0,0);
        split_transpose_v<<<dim3(SS/32, HDIM/32, BB*NH), dim3(32,8)>>>(pV, pVTs);

        // scores = Q' @ K'^T (batched over 32 bh; one 64-wide K-block -> T=3)
        mma_gemm<128,2,0><<<dim3(8,8,32), blk, SMEM128>>>(
            pQs, 2*DMODEL, 64, DMODEL, pKs, 2*DMODEL, 64, DMODEL, nullptr, nullptr,
            pP, SS, 0, 3,
            NH, (long)SS*2*DMODEL, (long)HDIM,
                (long)SS*2*DMODEL, (long)HDIM,
            1, (long)SS*SS, 0);

        softmax_split_kernel<<<BB*NH*SS, blk>>>(pP, pPs);

        // attn @ V -> split AO (head-merged layout)  (K=1024 -> T=48)
        mma_gemm<64,3,1><<<dim3(1,8,32), blk, SMEM64>>>(
            pPs, 2*SS, 64, SS, pVTs, 2*SS, 64, SS, nullptr, nullptr,
            pAOs, 2*DMODEL, DMODEL, 48,
            1, (long)SS*2*SS, 0, (long)HDIM*2*SS, 0,
            NH, (long)SS*2*DMODEL, (long)HDIM);

        // output projection -> fp32 T1  (NT=64, 3-stage)
        split_kernel<<<(DMODEL * DMODEL) / 1024, blk>>>(Wo_l, pWs, (long)DMODEL * DMODEL, 10);
        mma_gemm<64,3,0><<<dim3(16,16,1), blk, SMEM64>>>(
            pAOs, 2*DMODEL, 64, DMODEL, pWs, 2*DMODEL, 64, DMODEL, bo_l, nullptr,
            pT1, DMODEL, 0, 48, 1, 0,0,0,0, 1, 0,0);

        ln_kernel<<<NTOK, blk>>>(xin, pT1, g1_l, be1_l, pX1, pX1s);

        // FFN1 (gelu) -> split Hs   (grid 512 stays NT=128, 2-stage)
        split_kernel<<<(DFFN * DMODEL) / 1024, blk>>>(W1_l, pWs, (long)DFFN * DMODEL, 10);
        mma_gemm<128,2,2><<<dim3(32,16,1), blk, SMEM128>>>(
            pX1s, 2*DMODEL, 64, DMODEL, pWs, 2*DMODEL, 64, DMODEL, b1_l, nullptr,
            pHs, 2*DFFN, DFFN, 48, 1, 0,0,0,0, 1, 0,0);

        // FFN2 -> fp32 T1   (K=4096 -> T=192, NT=64, 3-stage)
        split_kernel<<<(DMODEL * DFFN) / 1024, blk>>>(W2_l, pWs, (long)DMODEL * DFFN, 12);
        mma_gemm<64,3,0><<<dim3(16,16,1), blk, SMEM64>>>(
            pHs, 2*DFFN, 64, DFFN, pWs, 2*DFFN, 64, DFFN, b2_l, nullptr,
            pT1, DMODEL, 0, 192, 1, 0,0,0,0, 1, 0,0);

        ln_kernel<<<NTOK, blk>>>(pX1, pT1, g2_l, be2_l, (l == NLAYER-1) ? out : pX, pXs);
    }
}

// round 8
// speedup vs baseline: 1.1686x; 1.1686x over previous
#include <cuda_runtime.h>
#include <cuda_bf16.h>
#include <cstdint>
#include <math.h>

#define BB   2
#define SS   1024
#define DMODEL 1024
#define NH   16
#define NLAYER 4
#define DFFN 4096
#define HDIM 64
#define NTOK (BB*SS)          // 2048
#define NREL (2*SS-1)         // 2047

// ---------------- static scratch ----------------
__device__ float          g_X  [NTOK*DMODEL];            // fp32 activations
__device__ __nv_bfloat16  g_Xs [NTOK*2*DMODEL];          // split of layer input
__device__ __nv_bfloat16  g_Qs [NTOK*2*DMODEL];
__device__ __nv_bfloat16  g_Ks [NTOK*2*DMODEL];          // split of K' = K/8 + Ebar
__device__ float          g_V  [NTOK*DMODEL];
__device__ __nv_bfloat16  g_VTs[(size_t)BB*NH*HDIM*2*SS];// per-head V^T split
__device__ float          g_P  [(size_t)BB*NH*SS*SS];    // scores fp32
__device__ __nv_bfloat16  g_Ps [(size_t)BB*NH*SS*2*SS];  // probs split
__device__ __nv_bfloat16  g_AOs[NTOK*2*DMODEL];
__device__ float          g_T1 [NTOK*DMODEL];
__device__ float          g_X1 [NTOK*DMODEL];
__device__ __nv_bfloat16  g_X1s[NTOK*2*DMODEL];
__device__ __nv_bfloat16  g_Hs [(size_t)NTOK*2*DFFN];
__device__ __nv_bfloat16  g_Ws [(size_t)DFFN*2*DMODEL];  // weight split scratch (16MB)
__device__ float          g_EB [SS*HDIM];

// ---------------- helpers ----------------
__device__ __forceinline__ uint32_t smem_to_u32(const void* p) {
    uint32_t a;
    asm("{ .reg .u64 t; cvta.to.shared.u64 t, %1; cvt.u32.u64 %0, t; }" : "=r"(a) : "l"(p));
    return a;
}
__device__ __forceinline__ void cp_async16(uint32_t s, const void* g) {
    asm volatile("cp.async.cg.shared.global [%0], [%1], 16;" :: "r"(s), "l"(g) : "memory");
}
#define CP_COMMIT() asm volatile("cp.async.commit_group;" ::: "memory")
#define CP_WAIT(n)  asm volatile("cp.async.wait_group %0;" :: "n"(n) : "memory")

__device__ __forceinline__ void ldsm_x4(uint32_t addr, uint32_t& r0, uint32_t& r1,
                                        uint32_t& r2, uint32_t& r3) {
    asm volatile("ldmatrix.sync.aligned.m8n8.x4.shared.b16 {%0,%1,%2,%3}, [%4];"
                 : "=r"(r0), "=r"(r1), "=r"(r2), "=r"(r3) : "r"(addr));
}
__device__ __forceinline__ void mma16816(float* c, const uint32_t* a, uint32_t b0, uint32_t b1) {
    asm volatile(
        "mma.sync.aligned.m16n8k16.row.col.f32.bf16.bf16.f32 "
        "{%0,%1,%2,%3}, {%4,%5,%6,%7}, {%8,%9}, {%0,%1,%2,%3};"
        : "+f"(c[0]), "+f"(c[1]), "+f"(c[2]), "+f"(c[3])
        : "r"(a[0]), "r"(a[1]), "r"(a[2]), "r"(a[3]), "r"(b0), "r"(b1));
}

struct __align__(8) bh4 { __nv_bfloat16 h[4]; };
__device__ __forceinline__ void split2(float v, __nv_bfloat16& hi, __nv_bfloat16& lo) {
    hi = __float2bfloat16(v);
    lo = __float2bfloat16(v - __bfloat162float(hi));
}

// =======================================================================
// HMMA split-fp32 GEMM: C = A * B^T with 3-term error compensation.
// A, B stored as [hi(K) | lo(K)] bf16 rows.
// NEW: one stage = one 64-wide K-block carrying Ahi+Alo+Bhi+Blo.
// Per k16: ldsm Ahi,Bhi -> mma hihi; ldsm Alo -> mma lohi (Bhi reused in
// regs); ldsm Blo -> mma hilo (Ahi reused). 8 LDSM per 24 MMA (was 12),
// global tiles 4/stage (was 6), stages T = K/64 (was 3x that).
// block tile 128 x 64, 8 warps = 4(m) x 2(n), 2-stage cp.async buffer.
// EPI: 0 = f32+bias, 1 = split+bias, 2 = split+bias+gelu, 3 = split+bias+kadjust
// =======================================================================
template<int EPI>
__global__ void __launch_bounds__(256) mma_gemm(
    const __nv_bfloat16* __restrict__ A, long lda, long csA, long loA,
    const __nv_bfloat16* __restrict__ B, long ldb, long csB, long loB,
    const float* __restrict__ bias, const float* __restrict__ EB,
    void* __restrict__ Cv, long ldc, long loOff,
    int T, int zdivAB, long sA1, long sA2, long sB1, long sB2,
    int zdivC, long sC1, long sC2)
{
    constexpr int NT = 64;
    extern __shared__ __align__(16) char smraw[];
    constexpr int LDS = 72;                   // bf16 elems per smem row (144B)
    constexpr int ASZ = 128 * LDS * 2;        // bytes per A tile (18432)
    constexpr int BSZ = NT  * LDS * 2;        // bytes per B tile (9216)
    constexpr int STAGE = 2 * ASZ + 2 * BSZ;  // Ahi|Alo|Bhi|Blo = 55296

    const int tid = threadIdx.x;
    const int z = blockIdx.z;
    A += (long)(z / zdivAB) * sA1 + (long)(z % zdivAB) * sA2;
    B += (long)(z / zdivAB) * sB1 + (long)(z % zdivAB) * sB2;
    const long co = (long)(z / zdivC) * sC1 + (long)(z % zdivC) * sC2;
    const int m0 = blockIdx.y * 128, n0 = blockIdx.x * NT;

    const int lane = tid & 31, wid = tid >> 5;
    const int warp_m = wid & 3, warp_n = wid >> 2;

    // load one K-block: Ahi, Alo (128x64), Bhi, Blo (64x64)
    auto load_stage = [&](int buf, int i) {
        const uint32_t base = smem_to_u32(smraw + (long)buf * STAGE);
        const long colA = (long)i * csA;
        const long colB = (long)i * csB;
        #pragma unroll
        for (int h = 0; h < 2; h++) {
            const long ca = colA + (h ? loA : 0);
            const uint32_t sa = base + h * ASZ;
            #pragma unroll
            for (int it = 0; it < 4; it++) {
                const int idx = tid + it * 256;
                const int row = idx >> 3, c = idx & 7;
                cp_async16(sa + row * (LDS * 2) + c * 16,
                           A + (long)(m0 + row) * lda + ca + c * 8);
            }
        }
        #pragma unroll
        for (int h = 0; h < 2; h++) {
            const long cb = colB + (h ? loB : 0);
            const uint32_t sb = base + 2 * ASZ + h * BSZ;
            #pragma unroll
            for (int it = 0; it < 2; it++) {
                const int idx = tid + it * 256;
                const int row = idx >> 3, c = idx & 7;
                cp_async16(sb + row * (LDS * 2) + c * 16,
                           B + (long)(n0 + row) * ldb + cb + c * 8);
            }
        }
        CP_COMMIT();
    };

    float acc[2][4][4];
    #pragma unroll
    for (int mi = 0; mi < 2; mi++)
        #pragma unroll
        for (int ni = 0; ni < 4; ni++)
            #pragma unroll
            for (int j = 0; j < 4; j++) acc[mi][ni][j] = 0.f;

    // ldmatrix lane selectors
    const int aRow = (lane & 7) + ((lane >> 3) & 1) * 8;   // within m16
    const int aK   = (lane >> 4) * 8;                      // within k16
    const int bN   = ((lane >> 4) * 8) + (lane & 7);       // within n16
    const int bK   = ((lane >> 3) & 1) * 8;                // within k16

    auto compute_stage = [&](int buf) {
        const uint32_t base = smem_to_u32(smraw + (long)buf * STAGE);
        const uint32_t sAhi = base, sAlo = base + ASZ;
        const uint32_t sBhi = base + 2 * ASZ, sBlo = sBhi + BSZ;
        #pragma unroll
        for (int k16 = 0; k16 < 4; k16++) {
            const int ka = k16 * 16 + aK;
            const int kb = k16 * 16 + bK;
            uint32_t ah[2][4], al[2][4], bh[2][4], bl[2][4];
            #pragma unroll
            for (int mi = 0; mi < 2; mi++) {
                const int m = warp_m * 32 + mi * 16 + aRow;
                ldsm_x4(sAhi + (m * LDS + ka) * 2, ah[mi][0], ah[mi][1], ah[mi][2], ah[mi][3]);
            }
            #pragma unroll
            for (int nb = 0; nb < 2; nb++) {
                const int n = warp_n * 32 + nb * 16 + bN;
                ldsm_x4(sBhi + (n * LDS + kb) * 2, bh[nb][0], bh[nb][1], bh[nb][2], bh[nb][3]);
            }
            #pragma unroll
            for (int mi = 0; mi < 2; mi++)
                #pragma unroll
                for (int ni = 0; ni < 4; ni++)
                    mma16816(acc[mi][ni], ah[mi], bh[ni >> 1][(ni & 1) * 2], bh[ni >> 1][(ni & 1) * 2 + 1]);
            // lo(A) x hi(B)
            #pragma unroll
            for (int mi = 0; mi < 2; mi++) {
                const int m = warp_m * 32 + mi * 16 + aRow;
                ldsm_x4(sAlo + (m * LDS + ka) * 2, al[mi][0], al[mi][1], al[mi][2], al[mi][3]);
            }
            #pragma unroll
            for (int mi = 0; mi < 2; mi++)
                #pragma unroll
                for (int ni = 0; ni < 4; ni++)
                    mma16816(acc[mi][ni], al[mi], bh[ni >> 1][(ni & 1) * 2], bh[ni >> 1][(ni & 1) * 2 + 1]);
            // hi(A) x lo(B)
            #pragma unroll
            for (int nb = 0; nb < 2; nb++) {
                const int n = warp_n * 32 + nb * 16 + bN;
                ldsm_x4(sBlo + (n * LDS + kb) * 2, bl[nb][0], bl[nb][1], bl[nb][2], bl[nb][3]);
            }
            #pragma unroll
            for (int mi = 0; mi < 2; mi++)
                #pragma unroll
                for (int ni = 0; ni < 4; ni++)
                    mma16816(acc[mi][ni], ah[mi], bl[ni >> 1][(ni & 1) * 2], bl[ni >> 1][(ni & 1) * 2 + 1]);
        }
    };

    load_stage(0, 0);
    for (int t = 0; t < T; t++) {
        if (t + 1 < T) { load_stage((t + 1) & 1, t + 1); CP_WAIT(1); }
        else           { CP_WAIT(0); }
        __syncthreads();
        compute_stage(t & 1);
        __syncthreads();
    }

    // ---------------- epilogue ----------------
    const int g = lane >> 2, tig = lane & 3;
    #pragma unroll
    for (int mi = 0; mi < 2; mi++) {
        #pragma unroll
        for (int ni = 0; ni < 4; ni++) {
            #pragma unroll
            for (int half = 0; half < 2; half++) {
                const int r = m0 + warp_m * 32 + mi * 16 + g + half * 8;
                const int c = n0 + warp_n * 32 + ni * 8 + tig * 2;
                float v0 = acc[mi][ni][half * 2 + 0];
                float v1 = acc[mi][ni][half * 2 + 1];
                if (bias) { v0 += bias[c]; v1 += bias[c + 1]; }
                if (EPI == 3) {
                    const int sr = (r & (SS - 1)) * HDIM;
                    v0 = v0 * 0.125f + EB[sr + (c & (HDIM - 1))];
                    v1 = v1 * 0.125f + EB[sr + ((c + 1) & (HDIM - 1))];
                }
                if (EPI == 2) {
                    v0 = 0.5f * v0 * (1.0f + erff(v0 * 0.70710678118654752f));
                    v1 = 0.5f * v1 * (1.0f + erff(v1 * 0.70710678118654752f));
                }
                if (EPI == 0) {
                    float* C = (float*)Cv + co;
                    float2 o; o.x = v0; o.y = v1;
                    *(float2*)&C[(long)r * ldc + c] = o;
                } else {
                    __nv_bfloat16* Cs = (__nv_bfloat16*)Cv + co;
                    __nv_bfloat16 h0, l0, h1, l1;
                    split2(v0, h0, l0); split2(v1, h1, l1);
                    __nv_bfloat162 hp, lp;
                    hp.x = h0; hp.y = h1; lp.x = l0; lp.y = l1;
                    *(__nv_bfloat162*)&Cs[(long)r * ldc + c]         = hp;
                    *(__nv_bfloat162*)&Cs[(long)r * ldc + c + loOff] = lp;
                }
            }
        }
    }
}

// ---------------- reductions ----------------
__device__ __forceinline__ float block_reduce_sum(float v, float* sh) {
    #pragma unroll
    for (int o = 16; o; o >>= 1) v += __shfl_xor_sync(0xffffffffu, v, o);
    int warp = threadIdx.x >> 5, lane = threadIdx.x & 31;
    if (lane == 0) sh[warp] = v;
    __syncthreads();
    if (threadIdx.x < 8) {
        float x = sh[threadIdx.x];
        #pragma unroll
        for (int o = 4; o; o >>= 1) x += __shfl_xor_sync(0xffu, x, o);
        if (threadIdx.x == 0) sh[0] = x;
    }
    __syncthreads();
    float r = sh[0];
    __syncthreads();
    return r;
}
__device__ __forceinline__ float block_reduce_max(float v, float* sh) {
    #pragma unroll
    for (int o = 16; o; o >>= 1) v = fmaxf(v, __shfl_xor_sync(0xffffffffu, v, o));
    int warp = threadIdx.x >> 5, lane = threadIdx.x & 31;
    if (lane == 0) sh[warp] = v;
    __syncthreads();
    if (threadIdx.x < 8) {
        float x = sh[threadIdx.x];
        #pragma unroll
        for (int o = 4; o; o >>= 1) x = fmaxf(x, __shfl_xor_sync(0xffu, x, o));
        if (threadIdx.x == 0) sh[0] = x;
    }
    __syncthreads();
    float r = sh[0];
    __syncthreads();
    return r;
}

// ---------------- Ebar ----------------
__global__ void ebar_kernel(const float* __restrict__ rel) {
    const int j = blockIdx.x, d = threadIdx.x;
    const float* r0 = rel + (long)(SS - 1 - j) * HDIM + d;
    float s = 0.f;
    #pragma unroll 4
    for (int k = 0; k < SS; k++) s += r0[(long)k * HDIM];
    g_EB[j * HDIM + d] = s * (1.0f / SS);
}

// ---------------- split fp32 [R,K] -> bf16 [R, 2K] ----------------
__global__ void __launch_bounds__(256) split_kernel(
    const float* __restrict__ in, __nv_bfloat16* __restrict__ out, long n, int kshift)
{
    const long i4 = ((long)blockIdx.x * 256 + threadIdx.x) * 4;
    if (i4 >= n) return;
    const long row = i4 >> kshift;
    const int  K   = 1 << kshift;
    const int  col = (int)(i4 & (K - 1));
    const float4 v = *(const float4*)&in[i4];
    bh4 hi, lo;
    split2(v.x, hi.h[0], lo.h[0]); split2(v.y, hi.h[1], lo.h[1]);
    split2(v.z, hi.h[2], lo.h[2]); split2(v.w, hi.h[3], lo.h[3]);
    *(bh4*)&out[row * 2 * K + col]     = hi;
    *(bh4*)&out[row * 2 * K + K + col] = lo;
}

// ---------------- V -> per-head V^T split ----------------
__global__ void split_transpose_v(const float* __restrict__ V, __nv_bfloat16* __restrict__ VT) {
    __shared__ float t[32][33];
    const int bh = blockIdx.z, b = bh >> 4, h = bh & 15;
    const int s0 = blockIdx.x * 32, d0 = blockIdx.y * 32;
    const int tx = threadIdx.x, ty = threadIdx.y;
    #pragma unroll
    for (int r = 0; r < 4; r++) {
        const int s = s0 + ty + r * 8;
        t[ty + r * 8][tx] = V[((long)b * SS + s) * DMODEL + h * HDIM + d0 + tx];
    }
    __syncthreads();
    #pragma unroll
    for (int r = 0; r < 4; r++) {
        const int d = d0 + ty + r * 8;
        const int s = s0 + tx;
        const float v = t[tx][ty + r * 8];
        __nv_bfloat16 hi, lo; split2(v, hi, lo);
        VT[((long)bh * HDIM + d) * (2 * SS) + s]      = hi;
        VT[((long)bh * HDIM + d) * (2 * SS) + SS + s] = lo;
    }
}

// ---------------- softmax (fp32 in) -> split bf16 out ----------------
__global__ void __launch_bounds__(256) softmax_split_kernel(
    const float* __restrict__ P, __nv_bfloat16* __restrict__ Ps)
{
    __shared__ float sh[8];
    const float* p = P + (long)blockIdx.x * SS;
    __nv_bfloat16* q = Ps + (long)blockIdx.x * (2 * SS);
    const int t = threadIdx.x;
    float4 v = *(const float4*)&p[t * 4];
    float m = fmaxf(fmaxf(v.x, v.y), fmaxf(v.z, v.w));
    m = block_reduce_max(m, sh);
    v.x = expf(v.x - m); v.y = expf(v.y - m);
    v.z = expf(v.z - m); v.w = expf(v.w - m);
    float s = v.x + v.y + v.z + v.w;
    s = block_reduce_sum(s, sh);
    const float inv = 1.0f / s;
    v.x *= inv; v.y *= inv; v.z *= inv; v.w *= inv;
    bh4 hi, lo;
    split2(v.x, hi.h[0], lo.h[0]); split2(v.y, hi.h[1], lo.h[1]);
    split2(v.z, hi.h[2], lo.h[2]); split2(v.w, hi.h[3], lo.h[3]);
    *(bh4*)&q[t * 4]      = hi;
    *(bh4*)&q[SS + t * 4] = lo;
}

// ---------------- LN(xin + add) -> fp32 out + split out ----------------
__global__ void __launch_bounds__(256) ln_kernel(
    const float* __restrict__ xin, const float* __restrict__ add,
    const float* __restrict__ g, const float* __restrict__ be,
    float* __restrict__ out, __nv_bfloat16* __restrict__ outs)
{
    __shared__ float sh[8];
    const long row = blockIdx.x;
    const int t = threadIdx.x;
    const float4 a  = *(const float4*)&xin[row * DMODEL + t * 4];
    const float4 b2 = *(const float4*)&add[row * DMODEL + t * 4];
    float y[4] = {a.x + b2.x, a.y + b2.y, a.z + b2.z, a.w + b2.w};
    float s = y[0] + y[1] + y[2] + y[3];
    s = block_reduce_sum(s, sh);
    const float mean = s * (1.0f / DMODEL);
    float q = 0.f;
    #pragma unroll
    for (int i = 0; i < 4; i++) { const float d = y[i] - mean; q += d * d; }
    q = block_reduce_sum(q, sh);
    const float rstd = rsqrtf(q * (1.0f / DMODEL) + 1e-5f);
    const float4 gg = *(const float4*)&g[t * 4];
    const float4 bb = *(const float4*)&be[t * 4];
    float o[4];
    o[0] = (y[0] - mean) * rstd * gg.x + bb.x;
    o[1] = (y[1] - mean) * rstd * gg.y + bb.y;
    o[2] = (y[2] - mean) * rstd * gg.z + bb.z;
    o[3] = (y[3] - mean) * rstd * gg.w + bb.w;
    *(float4*)&out[row * DMODEL + t * 4] = *(float4*)o;
    bh4 hi, lo;
    #pragma unroll
    for (int i = 0; i < 4; i++) split2(o[i], hi.h[i], lo.h[i]);
    *(bh4*)&outs[row * 2 * DMODEL + t * 4]          = hi;
    *(bh4*)&outs[row * 2 * DMODEL + DMODEL + t * 4] = lo;
}

// ---------------- host ----------------
extern "C" void kernel_launch(void* const* d_in, const int* in_sizes, int n_in,
                              void* d_out, int out_size)
{
    (void)in_sizes; (void)n_in; (void)out_size;
    const float* x   = (const float*)d_in[0];
    const float* Wq  = (const float*)d_in[1];
    const float* bq  = (const float*)d_in[2];
    const float* Wk  = (const float*)d_in[3];
    const float* bk  = (const float*)d_in[4];
    const float* Wv  = (const float*)d_in[5];
    const float* bv  = (const float*)d_in[6];
    const float* Wo  = (const float*)d_in[7];
    const float* bo  = (const float*)d_in[8];
    const float* rel = (const float*)d_in[9];
    const float* W1  = (const float*)d_in[10];
    const float* b1  = (const float*)d_in[11];
    const float* W2  = (const float*)d_in[12];
    const float* b2  = (const float*)d_in[13];
    const float* g1  = (const float*)d_in[14];
    const float* be1 = (const float*)d_in[15];
    const float* g2  = (const float*)d_in[16];
    const float* be2 = (const float*)d_in[17];
    float* out = (float*)d_out;

    float *pX, *pV, *pP, *pT1, *pX1, *pEB;
    __nv_bfloat16 *pXs, *pQs, *pKs, *pVTs, *pPs, *pAOs, *pX1s, *pHs, *pWs;
    cudaGetSymbolAddress((void**)&pX,   g_X);
    cudaGetSymbolAddress((void**)&pXs,  g_Xs);
    cudaGetSymbolAddress((void**)&pQs,  g_Qs);
    cudaGetSymbolAddress((void**)&pKs,  g_Ks);
    cudaGetSymbolAddress((void**)&pV,   g_V);
    cudaGetSymbolAddress((void**)&pVTs, g_VTs);
    cudaGetSymbolAddress((void**)&pP,   g_P);
    cudaGetSymbolAddress((void**)&pPs,  g_Ps);
    cudaGetSymbolAddress((void**)&pAOs, g_AOs);
    cudaGetSymbolAddress((void**)&pT1,  g_T1);
    cudaGetSymbolAddress((void**)&pX1,  g_X1);
    cudaGetSymbolAddress((void**)&pX1s, g_X1s);
    cudaGetSymbolAddress((void**)&pHs,  g_Hs);
    cudaGetSymbolAddress((void**)&pWs,  g_Ws);
    cudaGetSymbolAddress((void**)&pEB,  g_EB);

    constexpr int LDS = 72;
    const int STAGE = 2 * (128 * LDS * 2) + 2 * (64 * LDS * 2);  // 55296
    const int SMEM  = 2 * STAGE;                                 // 110592
    cudaFuncSetAttribute((void*)mma_gemm<0>, cudaFuncAttributeMaxDynamicSharedMemorySize, SMEM);
    cudaFuncSetAttribute((void*)mma_gemm<1>, cudaFuncAttributeMaxDynamicSharedMemorySize, SMEM);
    cudaFuncSetAttribute((void*)mma_gemm<2>, cudaFuncAttributeMaxDynamicSharedMemorySize, SMEM);
    cudaFuncSetAttribute((void*)mma_gemm<3>, cudaFuncAttributeMaxDynamicSharedMemorySize, SMEM);

    const dim3 blk(256);

    // split the initial input once
    split_kernel<<<(NTOK * DMODEL) / 1024, blk>>>(x, pXs, (long)NTOK * DMODEL, 10);

    for (int l = 0; l < NLAYER; l++) {
        const float* xin  = (l == 0) ? x : pX;
        const float* Wq_l = Wq + (long)l * DMODEL * DMODEL;
        const float* Wk_l = Wk + (long)l * DMODEL * DMODEL;
        const float* Wv_l = Wv + (long)l * DMODEL * DMODEL;
        const float* Wo_l = Wo + (long)l * DMODEL * DMODEL;
        const float* W1_l = W1 + (long)l * DFFN * DMODEL;
        const float* W2_l = W2 + (long)l * DMODEL * DFFN;
        const float* bq_l = bq + (long)l * DMODEL;
        const float* bk_l = bk + (long)l * DMODEL;
        const float* bv_l = bv + (long)l * DMODEL;
        const float* bo_l = bo + (long)l * DMODEL;
        const float* b1_l = b1 + (long)l * DFFN;
        const float* b2_l = b2 + (long)l * DMODEL;
        const float* g1_l = g1 + (long)l * DMODEL;
        const float* be1_l= be1+ (long)l * DMODEL;
        const float* g2_l = g2 + (long)l * DMODEL;
        const float* be2_l= be2+ (long)l * DMODEL;
        const float* rel_l= rel+ (long)l * NREL * HDIM;

        ebar_kernel<<<SS, HDIM>>>(rel_l);

        // Q projection -> split Qs  (T = 1024/64 = 16 K-blocks)
        split_kernel<<<(DMODEL * DMODEL) / 1024, blk>>>(Wq_l, pWs, (long)DMODEL * DMODEL, 10);
        mma_gemm<1><<<dim3(16,16,1), blk, SMEM>>>(
            pXs, 2*DMODEL, 64, DMODEL, pWs, 2*DMODEL, 64, DMODEL, bq_l, nullptr,
            pQs, 2*DMODEL, DMODEL, 16, 1, 0,0,0,0, 1, 0,0);

        // K projection -> K' = K/8 + Ebar -> split Ks
        split_kernel<<<(DMODEL * DMODEL) / 1024, blk>>>(Wk_l, pWs, (long)DMODEL * DMODEL, 10);
        mma_gemm<3><<<dim3(16,16,1), blk, SMEM>>>(
            pXs, 2*DMODEL, 64, DMODEL, pWs, 2*DMODEL, 64, DMODEL, bk_l, pEB,
            pKs, 2*DMODEL, DMODEL, 16, 1, 0,0,0,0, 1, 0,0);

        // V projection -> fp32 V
        split_kernel<<<(DMODEL * DMODEL) / 1024, blk>>>(Wv_l, pWs, (long)DMODEL * DMODEL, 10);
        mma_gemm<0><<<dim3(16,16,1), blk, SMEM>>>(
            pXs, 2*DMODEL, 64, DMODEL, pWs, 2*DMODEL, 64, DMODEL, bv_l, nullptr,
            pV, DMODEL, 0, 16, 1, 0,0,0,0, 1, 0,0);
        split_transpose_v<<<dim3(SS/32, HDIM/32, BB*NH), dim3(32,8)>>>(pV, pVTs);

        // scores = Q' @ K'^T (batched over 32 bh; HDIM=64 -> T=1)
        mma_gemm<0><<<dim3(16,8,32), blk, SMEM>>>(
            pQs, 2*DMODEL, 64, DMODEL, pKs, 2*DMODEL, 64, DMODEL, nullptr, nullptr,
            pP, SS, 0, 1,
            NH, (long)SS*2*DMODEL, (long)HDIM,
                (long)SS*2*DMODEL, (long)HDIM,
            1, (long)SS*SS, 0);

        softmax_split_kernel<<<BB*NH*SS, blk>>>(pP, pPs);

        // attn @ V -> split AO (head-merged layout)  (K=1024 -> T=16)
        mma_gemm<1><<<dim3(1,8,32), blk, SMEM>>>(
            pPs, 2*SS, 64, SS, pVTs, 2*SS, 64, SS, nullptr, nullptr,
            pAOs, 2*DMODEL, DMODEL, 16,
            1, (long)SS*2*SS, 0, (long)HDIM*2*SS, 0,
            NH, (long)SS*2*DMODEL, (long)HDIM);

        // output projection -> fp32 T1
        split_kernel<<<(DMODEL * DMODEL) / 1024, blk>>>(Wo_l, pWs, (long)DMODEL * DMODEL, 10);
        mma_gemm<0><<<dim3(16,16,1), blk, SMEM>>>(
            pAOs, 2*DMODEL, 64, DMODEL, pWs, 2*DMODEL, 64, DMODEL, bo_l, nullptr,
            pT1, DMODEL, 0, 16, 1, 0,0,0,0, 1, 0,0);

        ln_kernel<<<NTOK, blk>>>(xin, pT1, g1_l, be1_l, pX1, pX1s);

        // FFN1 (gelu) -> split Hs   (N=4096 -> grid 64x16, T=16)
        split_kernel<<<(DFFN * DMODEL) / 1024, blk>>>(W1_l, pWs, (long)DFFN * DMODEL, 10);
        mma_gemm<2><<<dim3(64,16,1), blk, SMEM>>>(
            pX1s, 2*DMODEL, 64, DMODEL, pWs, 2*DMODEL, 64, DMODEL, b1_l, nullptr,
            pHs, 2*DFFN, DFFN, 16, 1, 0,0,0,0, 1, 0,0);

        // FFN2 -> fp32 T1   (K=4096 -> T=64)
        split_kernel<<<(DMODEL * DFFN) / 1024, blk>>>(W2_l, pWs, (long)DMODEL * DFFN, 12);
        mma_gemm<0><<<dim3(16,16,1), blk, SMEM>>>(
            pHs, 2*DFFN, 64, DFFN, pWs, 2*DFFN, 64, DFFN, b2_l, nullptr,
            pT1, DMODEL, 0, 64, 1, 0,0,0,0, 1, 0,0);

        ln_kernel<<<NTOK, blk>>>(pX1, pT1, g2_l, be2_l, (l == NLAYER-1) ? out : pX, pXs);
    }
}